// round 14
// baseline (speedup 1.0000x reference)
#include <cuda_runtime.h>
#include <cuda/atomic>
#include <math.h>

#define H  96
#define W  96
#define HW (H*W)
#define MAXB 8
#define COLS_PB 16                      // columns per block
#define PX_PT  2                        // adjacent-column pixels per thread
#define BLK_PER_B (W / COLS_PB)         // 6 blocks per batch image
#define NTHR 768                        // 96 rows x 8 col-pairs
// sentinel: real max d^2 = 2*95^2 = 18050 < 23742, and 23742+95^2 = 32767
// fits the 15-bit field. best >= SENT  <=>  no opposite pixel exists.
#define SENT 23742
#define BIGV 0x7FFF

// Scratch (allocation-free rule: __device__ globals; zero-initialized).
// 16 float2-slots per batch; only 6 written, rest stay 0 forever.
__device__ float g_part[MAXB * 32];
__device__ int   g_ticket;              // winner resets -> replay-safe

// distance from position w (0..95) to nearest set bit in 96-bit mask
// (lo = bits 0..63, hi = bits 64..95 in its low 32). >=96 if none.
__device__ __forceinline__ int nearest_bit_dist(unsigned long long lo,
                                                unsigned long long hi, int w) {
    int dr;
    if (w < 64) {
        unsigned long long l = (lo >> w) | ((hi << 1) << (63 - w));
        unsigned long long h2 = hi >> w;
        dr = l ? (__ffsll((long long)l) - 1)
               : (h2 ? 64 + (__ffsll((long long)h2) - 1) : 1000);
    } else {
        unsigned long long l = hi >> (w - 64);
        dr = l ? (__ffsll((long long)l) - 1) : 1000;
    }
    const int wp = w + 1;
    unsigned long long mlo = (wp >= 64) ? lo : (lo & ((1ull << wp) - 1ull));
    unsigned long long mhi = (wp <= 64) ? 0ull : (hi & ((1ull << (wp - 64)) - 1ull));
    int dl;
    if (mhi)      dl = w - (127 - __clzll((long long)mhi));
    else if (mlo) dl = w - (63 - __clzll((long long)mlo));
    else          dl = 1000;
    return min(dl, dr);
}

__device__ __forceinline__ unsigned pack_g(int d) {
    return (d > 95) ? (unsigned)SENT : (unsigned)(d * d);
}

// consumer of class c needs: (cls(h')==c) ? gop^2(h') : 0
__device__ __forceinline__ int scan_val(unsigned x, unsigned cbit15) {
    return ((x ^ cbit15) & 0x8000u) ? 0 : (int)(x & 0x7FFFu);
}

__global__ void __launch_bounds__(NTHR, 1) dice_kernel(
        const float* __restrict__ inp,
        const int*   __restrict__ tgt,
        float* __restrict__ out, int B) {
    const int b    = blockIdx.x / BLK_PER_B;
    const int wc0  = (blockIdx.x % BLK_PER_B) * COLS_PB;
    const int t    = threadIdx.x;          // 0..767
    const int lane = t & 31;
    const int warp = t >> 5;               // 0..23
    const int nblk = gridDim.x;

    const int h  = t >> 3;                 // 0..95 (this thread's row)
    const int wl = (t & 7) * PX_PT;        // 0,2,..,14 (local col pair)
    const int wc = wc0 + wl;

    __shared__ unsigned       bitmap[HW / 32];     // 288 words: image as bits
    __shared__ unsigned short gcol[H * COLS_PB];   // gop^2 | (cls<<15), 16-bit
    __shared__ float          wred[2][NTHR / 32];
    __shared__ int            cnt_s[NTHR / 32];
    __shared__ int            n1_s;

    // phase-B operand: one 8B load (adjacent columns), issued immediately
    const float2 pv = *(const float2*)(inp + b * HW + h * W + wc);

    // ---- build image bitmap: 3 int4 rounds + 8-lane shfl-OR packing -------
    const int4* tb4 = (const int4*)(tgt + b * HW);
    const int sub = 4 * (lane & 7);            // nibble position in word
    int cnt = 0;
#pragma unroll
    for (int i = 0; i < HW / (NTHR * 4); ++i) {        // 3 rounds
        const int4 v = tb4[i * NTHR + t];
        const unsigned nib = (unsigned)(v.x | (v.y << 1) | (v.z << 2) | (v.w << 3));
        cnt += __popc(nib);
        unsigned wrd = nib << sub;
        wrd |= __shfl_xor_sync(0xFFFFFFFFu, wrd, 1);
        wrd |= __shfl_xor_sync(0xFFFFFFFFu, wrd, 2);
        wrd |= __shfl_xor_sync(0xFFFFFFFFu, wrd, 4);
        if ((lane & 7) == 0) bitmap[i * (NTHR / 8) + (t >> 3)] = wrd;
    }
    cnt = __reduce_add_sync(0xFFFFFFFFu, cnt);
    if (lane == 0) cnt_s[warp] = cnt;
    __syncthreads();

    if (warp == 0) {                               // class-1 count (exact)
        int s = (lane < NTHR / 32) ? cnt_s[lane] : 0;
        s = __reduce_add_sync(0xFFFFFFFFu, s);
        if (lane == 0) n1_s = s;
    }

    // ---- row EDT: ONE opposite-class query per pixel (own-class dist = 0) -
    const unsigned long long lo =
        (unsigned long long)bitmap[h * 3] |
        ((unsigned long long)bitmap[h * 3 + 1] << 32);
    const unsigned long long hi = (unsigned long long)bitmap[h * 3 + 2];
    const unsigned long long nlo = ~lo;
    const unsigned long long nhi = (~hi) & 0xFFFFFFFFull;

    const int c0 = (wc < 64) ? (int)((lo >> wc) & 1ull)
                             : (int)((hi >> (wc - 64)) & 1ull);
    const int c1 = ((wc + 1) < 64) ? (int)((lo >> (wc + 1)) & 1ull)
                                   : (int)((hi >> (wc + 1 - 64)) & 1ull);

    // class-c pixel queries the opposite-class mask
    const int dq0 = nearest_bit_dist(c0 ? nlo : lo, c0 ? nhi : hi, wc);
    const int dq1 = nearest_bit_dist(c1 ? nlo : lo, c1 ? nhi : hi, wc + 1);
    const unsigned e0 = pack_g(dq0) | ((unsigned)c0 << 15);
    const unsigned e1 = pack_g(dq1) | ((unsigned)c1 << 15);
    gcol[h * COLS_PB + wl]     = (unsigned short)e0;
    gcol[h * COLS_PB + wl + 1] = (unsigned short)e1;
    __syncthreads();

    const int n1 = n1_s;

    // ---- column scans: radii 1-2 unconditional, rare loop from r=3 --------
    float r1 = 0.0f, r2 = 0.0f;
#pragma unroll
    for (int px = 0; px < PX_PT; ++px) {
        const int col      = wl + px;
        const int c        = px ? c1 : c0;
        const unsigned cb  = (unsigned)c << 15;
        const int bi       = h * COLS_PB + col;
        int best = px ? (int)(e1 & 0x7FFFu) : (int)(e0 & 0x7FFFu);   // r=0
        const int vu1 = (h >= 1)     ? scan_val(gcol[bi - COLS_PB],     cb) : BIGV;
        const int vd1 = (h <= H - 2) ? scan_val(gcol[bi + COLS_PB],     cb) : BIGV;
        const int vu2 = (h >= 2)     ? scan_val(gcol[bi - 2 * COLS_PB], cb) : BIGV;
        const int vd2 = (h <= H - 3) ? scan_val(gcol[bi + 2 * COLS_PB], cb) : BIGV;
        best = min(best, min(1 + min(vu1, vd1), 4 + min(vu2, vd2)));
        for (int r = 3; r <= 95 && r * r < best; ++r) {
            const int rr = r * r;
            const int up = h - r, dn = h + r;
            if (up >= 0) best = min(best, rr + scan_val(gcol[up * COLS_PB + col], cb));
            if (dn < H)  best = min(best, rr + scan_val(gcol[dn * COLS_PB + col], cb));
        }
        // weight: 10*exp(-dmin/(2*5^2)); no opposite -> exp(-inf)=0; n1<=1 -> 1
        float wgt;
        if (n1 <= 1)           wgt = 1.0f;
        else if (best >= SENT) wgt = 0.0f;
        else                   wgt = 10.0f * __expf(-sqrtf((float)best) * 0.02f);
        const float p  = px ? pv.y : pv.x;
        const float tt = (float)c;
        r1 += wgt * p * tt;
        r2 += wgt * (p + tt);
    }

#pragma unroll
    for (int off = 16; off; off >>= 1) {
        r1 += __shfl_down_sync(0xFFFFFFFFu, r1, off);
        r2 += __shfl_down_sync(0xFFFFFFFFu, r2, off);
    }
    if (lane == 0) { wred[0][warp] = r1; wred[1][warp] = r2; }
    __syncthreads();

    if (warp == 0) {
        float s1 = (lane < NTHR / 32) ? wred[0][lane] : 0.0f;
        float s2 = (lane < NTHR / 32) ? wred[1][lane] : 0.0f;
#pragma unroll
        for (int off = 16; off; off >>= 1) {
            s1 += __shfl_down_sync(0xFFFFFFFFu, s1, off);
            s2 += __shfl_down_sync(0xFFFFFFFFu, s2, off);
        }
        int last = 0;
        if (lane == 0) {
            const int slot = blockIdx.x % BLK_PER_B;      // 0..5
            g_part[b * 32 + slot * 2 + 0] = s1;
            g_part[b * 32 + slot * 2 + 1] = s2;
            // release orders partial stores; acquire on the winning fetch_add
            // orders the winner's reads. No fence.sc -> no L1-flush.
            cuda::atomic_ref<int, cuda::thread_scope_device> tk(g_ticket);
            last = (tk.fetch_add(1, cuda::memory_order_acq_rel) == nblk - 1);
        }
        last = __shfl_sync(0xFFFFFFFFu, last, 0);

        // ---- winner: one-warp deterministic final combine + cleanup -------
        if (last) {
            // lanes 0..15 -> batch0 slots, 16..31 -> batch1 (unused slots=0)
            const int bb   = lane >> 4;
            const int slot = lane & 15;
            float t1 = 0.0f, t2 = 0.0f;
            if (bb < B) {
                cuda::atomic_ref<float, cuda::thread_scope_device>
                    a1(g_part[bb * 32 + slot * 2 + 0]),
                    a2(g_part[bb * 32 + slot * 2 + 1]);
                t1 = a1.load(cuda::memory_order_relaxed);
                t2 = a2.load(cuda::memory_order_relaxed);
            }
#pragma unroll
            for (int off = 8; off; off >>= 1) {            // within 16-group
                t1 += __shfl_xor_sync(0xFFFFFFFFu, t1, off);
                t2 += __shfl_xor_sync(0xFFFFFFFFu, t2, off);
            }
            float loss = 1.0f - (2.0f * t1 + 1.0f) / (t2 + 1.0f);  // 0 if bb>=B
            loss += __shfl_xor_sync(0xFFFFFFFFu, loss, 16);        // batches
            if (lane == 0) {
                out[0] = loss;
                g_ticket = 0;      // replay-safe reset
            }
        }
    }
}

extern "C" void kernel_launch(void* const* d_in, const int* in_sizes, int n_in,
                              void* d_out, int out_size) {
    const float* inp = (const float*)d_in[0];   // inputs  [B,1,96,96] float32
    const int*   tgt = (const int*)  d_in[1];   // targets [B,1,96,96] int32
    const int B = in_sizes[1] / HW;

    dice_kernel<<<B * BLK_PER_B, NTHR>>>(inp, tgt, (float*)d_out, B);
}

// round 15
// speedup vs baseline: 1.0534x; 1.0534x over previous
#include <cuda_runtime.h>
#include <cuda/atomic>
#include <math.h>

#define H  96
#define W  96
#define HW (H*W)
#define MAXB 8
#define COLS_PB 8                       // columns per block
#define BLK_PER_B (W / COLS_PB)         // 12 blocks per batch image
#define NTHR 768                        // 96 rows x 8 cols = 1 px/thread
// sentinel: real max d^2 = 2*95^2 = 18050 < 23742; >= SENT <=> no opposite.
#define SENT 23742
#define BIGV 0x7FFF

// Scratch (allocation-free rule: __device__ globals; zero-initialized).
// Accumulators start at 0; winner resets them + ticket after reading.
__device__ float g_acc[MAXB * 2];       // per-batch (num, den) accumulators
__device__ int   g_ticket;

// distance from position w (0..95) to nearest set bit in 96-bit mask
// (lo = bits 0..63, hi = bits 64..95 in its low 32). >=96 if none.
__device__ __forceinline__ int nearest_bit_dist(unsigned long long lo,
                                                unsigned long long hi, int w) {
    int dr;
    if (w < 64) {
        unsigned long long l = (lo >> w) | ((hi << 1) << (63 - w));
        unsigned long long h2 = hi >> w;
        dr = l ? (__ffsll((long long)l) - 1)
               : (h2 ? 64 + (__ffsll((long long)h2) - 1) : 1000);
    } else {
        unsigned long long l = hi >> (w - 64);
        dr = l ? (__ffsll((long long)l) - 1) : 1000;
    }
    const int wp = w + 1;
    unsigned long long mlo = (wp >= 64) ? lo : (lo & ((1ull << wp) - 1ull));
    unsigned long long mhi = (wp <= 64) ? 0ull : (hi & ((1ull << (wp - 64)) - 1ull));
    int dl;
    if (mhi)      dl = w - (127 - __clzll((long long)mhi));
    else if (mlo) dl = w - (63 - __clzll((long long)mlo));
    else          dl = 1000;
    return min(dl, dr);
}

__device__ __forceinline__ unsigned pack_g(int d) {
    return (d > 95) ? (unsigned)SENT : (unsigned)(d * d);
}

// consumer of class c needs: (cls(h')==c) ? gop^2(h') : 0
__device__ __forceinline__ int scan_val(unsigned x, unsigned cbit15) {
    return ((x ^ cbit15) & 0x8000u) ? 0 : (int)(x & 0x7FFFu);
}

__global__ void __launch_bounds__(NTHR, 1) dice_kernel(
        const float* __restrict__ inp,
        const int*   __restrict__ tgt,
        float* __restrict__ out, int B) {
    const int b    = blockIdx.x / BLK_PER_B;
    const int wc0  = (blockIdx.x % BLK_PER_B) * COLS_PB;
    const int t    = threadIdx.x;          // 0..767
    const int lane = t & 31;
    const int warp = t >> 5;               // 0..23
    const int nblk = gridDim.x;

    const int h  = t >> 3;                 // 0..95 (this thread's row)
    const int wl = t & 7;                  // 0..7  (local column)
    const int wc = wc0 + wl;

    __shared__ unsigned       bitmap[HW / 32];     // 288 words: image as bits
    __shared__ unsigned short gcol[H * COLS_PB];   // gop^2 | (cls<<15)
    __shared__ float          wred[2][NTHR / 32];
    __shared__ int            cnt_s[NTHR / 32];
    __shared__ int            n1_s;

    // phase-B operand issued immediately (latency hidden under bitmap build)
    const float p = inp[b * HW + h * W + wc];

    // ---- build image bitmap: 3 int4 rounds + 8-lane shfl-OR packing -------
    const int4* tb4 = (const int4*)(tgt + b * HW);
    const int sub = 4 * (lane & 7);            // nibble position in word
    int cnt = 0;
#pragma unroll
    for (int i = 0; i < HW / (NTHR * 4); ++i) {        // 3 rounds
        const int4 v = tb4[i * NTHR + t];
        const unsigned nib = (unsigned)(v.x | (v.y << 1) | (v.z << 2) | (v.w << 3));
        cnt += __popc(nib);
        unsigned wrd = nib << sub;
        wrd |= __shfl_xor_sync(0xFFFFFFFFu, wrd, 1);
        wrd |= __shfl_xor_sync(0xFFFFFFFFu, wrd, 2);
        wrd |= __shfl_xor_sync(0xFFFFFFFFu, wrd, 4);
        if ((lane & 7) == 0) bitmap[i * (NTHR / 8) + (t >> 3)] = wrd;
    }
    cnt = __reduce_add_sync(0xFFFFFFFFu, cnt);
    if (lane == 0) cnt_s[warp] = cnt;
    __syncthreads();

    if (warp == 0) {                               // class-1 count (exact)
        int s = (lane < NTHR / 32) ? cnt_s[lane] : 0;
        s = __reduce_add_sync(0xFFFFFFFFu, s);
        if (lane == 0) n1_s = s;
    }

    // ---- row EDT: ONE opposite-class query per pixel (own-class dist = 0) -
    const unsigned long long lo =
        (unsigned long long)bitmap[h * 3] |
        ((unsigned long long)bitmap[h * 3 + 1] << 32);
    const unsigned long long hi = (unsigned long long)bitmap[h * 3 + 2];

    const int c = (wc < 64) ? (int)((lo >> wc) & 1ull)
                            : (int)((hi >> (wc - 64)) & 1ull);
    const int dq = nearest_bit_dist(c ? ~lo : lo,
                                    c ? ((~hi) & 0xFFFFFFFFull) : hi, wc);
    const unsigned e = pack_g(dq) | ((unsigned)c << 15);
    gcol[h * COLS_PB + wl] = (unsigned short)e;
    __syncthreads();

    const int n1 = n1_s;

    // ---- column scan: radii 1-2 unconditional, rare loop from r=3 ---------
    const unsigned cb = (unsigned)c << 15;
    const int bi = h * COLS_PB + wl;
    int best = (int)(e & 0x7FFFu);                       // r = 0 term
    const int vu1 = (h >= 1)     ? scan_val(gcol[bi - COLS_PB],     cb) : BIGV;
    const int vd1 = (h <= H - 2) ? scan_val(gcol[bi + COLS_PB],     cb) : BIGV;
    const int vu2 = (h >= 2)     ? scan_val(gcol[bi - 2 * COLS_PB], cb) : BIGV;
    const int vd2 = (h <= H - 3) ? scan_val(gcol[bi + 2 * COLS_PB], cb) : BIGV;
    best = min(best, min(1 + min(vu1, vd1), 4 + min(vu2, vd2)));
    for (int r = 3; r <= 95 && r * r < best; ++r) {
        const int rr = r * r;
        const int up = h - r, dn = h + r;
        if (up >= 0) best = min(best, rr + scan_val(gcol[up * COLS_PB + wl], cb));
        if (dn < H)  best = min(best, rr + scan_val(gcol[dn * COLS_PB + wl], cb));
    }

    // weight: 10*exp(-dmin/(2*5^2)); no opposite -> exp(-inf)=0; n1<=1 -> 1
    float wgt;
    if (n1 <= 1)           wgt = 1.0f;
    else if (best >= SENT) wgt = 0.0f;
    else                   wgt = 10.0f * __expf(-sqrtf((float)best) * 0.02f);

    const float tt = (float)c;
    float r1 = wgt * p * tt;
    float r2 = wgt * (p + tt);
#pragma unroll
    for (int off = 16; off; off >>= 1) {
        r1 += __shfl_down_sync(0xFFFFFFFFu, r1, off);
        r2 += __shfl_down_sync(0xFFFFFFFFu, r2, off);
    }
    if (lane == 0) { wred[0][warp] = r1; wred[1][warp] = r2; }
    __syncthreads();

    if (warp == 0) {
        float s1 = (lane < NTHR / 32) ? wred[0][lane] : 0.0f;
        float s2 = (lane < NTHR / 32) ? wred[1][lane] : 0.0f;
#pragma unroll
        for (int off = 16; off; off >>= 1) {
            s1 += __shfl_down_sync(0xFFFFFFFFu, s1, off);
            s2 += __shfl_down_sync(0xFFFFFFFFu, s2, off);
        }
        int last = 0;
        if (lane == 0) {
            // accumulate directly onto per-batch totals (commutative adds;
            // ordering-induced wobble ~1e-7 rel, far under the 1e-3 gate)
            cuda::atomic_ref<float, cuda::thread_scope_device>
                a1(g_acc[b * 2 + 0]), a2(g_acc[b * 2 + 1]);
            a1.fetch_add(s1, cuda::memory_order_relaxed);
            a2.fetch_add(s2, cuda::memory_order_relaxed);
            // release orders the adds; acquire on the winning fetch_add
            // makes all blocks' adds visible to the winner. No L1-flush.
            cuda::atomic_ref<int, cuda::thread_scope_device> tk(g_ticket);
            last = (tk.fetch_add(1, cuda::memory_order_acq_rel) == nblk - 1);
        }
        last = __shfl_sync(0xFFFFFFFFu, last, 0);

        // ---- winner: 4 L2-hot loads, dice formula, cleanup ----------------
        if (last && lane == 0) {
            float loss = 0.0f;
#pragma unroll
            for (int bb = 0; bb < MAXB; ++bb) {
                if (bb < B) {
                    cuda::atomic_ref<float, cuda::thread_scope_device>
                        a1(g_acc[bb * 2 + 0]), a2(g_acc[bb * 2 + 1]);
                    const float n = a1.load(cuda::memory_order_relaxed);
                    const float d = a2.load(cuda::memory_order_relaxed);
                    loss += 1.0f - (2.0f * n + 1.0f) / (d + 1.0f);
                    a1.store(0.0f, cuda::memory_order_relaxed);  // next replay
                    a2.store(0.0f, cuda::memory_order_relaxed);
                }
            }
            out[0] = loss;
            g_ticket = 0;                                  // replay-safe reset
        }
    }
}

extern "C" void kernel_launch(void* const* d_in, const int* in_sizes, int n_in,
                              void* d_out, int out_size) {
    const float* inp = (const float*)d_in[0];   // inputs  [B,1,96,96] float32
    const int*   tgt = (const int*)  d_in[1];   // targets [B,1,96,96] int32
    const int B = in_sizes[1] / HW;

    dice_kernel<<<B * BLK_PER_B, NTHR>>>(inp, tgt, (float*)d_out, B);
}

// round 16
// speedup vs baseline: 1.0575x; 1.0038x over previous
#include <cuda_runtime.h>
#include <cuda/atomic>
#include <math.h>

#define H  96
#define W  96
#define HW (H*W)
#define MAXB 8
#define COLS_PB 8                       // columns per block
#define BLK_PER_B (W / COLS_PB)         // 12 blocks per batch image
#define NTHR 768                        // 96 rows x 8 cols = 1 px/thread
// sentinel: real max d^2 = 2*95^2 = 18050 < 23742; >= SENT <=> no opposite.
#define SENT 23742
#define BIGV 0x7FFF

// Scratch (allocation-free rule: __device__ globals; zero-initialized).
// Accumulators start at 0; winner resets them + ticket after reading.
__device__ __align__(16) float g_acc[MAXB * 2];   // per-batch (num, den)
__device__ int g_ticket;

// distance from position w (0..95) to nearest set bit in 96-bit mask
// (lo = bits 0..63, hi = bits 64..95 in its low 32). >=96 if none.
__device__ __forceinline__ int nearest_bit_dist(unsigned long long lo,
                                                unsigned long long hi, int w) {
    int dr;
    if (w < 64) {
        unsigned long long l = (lo >> w) | ((hi << 1) << (63 - w));
        unsigned long long h2 = hi >> w;
        dr = l ? (__ffsll((long long)l) - 1)
               : (h2 ? 64 + (__ffsll((long long)h2) - 1) : 1000);
    } else {
        unsigned long long l = hi >> (w - 64);
        dr = l ? (__ffsll((long long)l) - 1) : 1000;
    }
    const int wp = w + 1;
    unsigned long long mlo = (wp >= 64) ? lo : (lo & ((1ull << wp) - 1ull));
    unsigned long long mhi = (wp <= 64) ? 0ull : (hi & ((1ull << (wp - 64)) - 1ull));
    int dl;
    if (mhi)      dl = w - (127 - __clzll((long long)mhi));
    else if (mlo) dl = w - (63 - __clzll((long long)mlo));
    else          dl = 1000;
    return min(dl, dr);
}

__device__ __forceinline__ unsigned pack_g(int d) {
    return (d > 95) ? (unsigned)SENT : (unsigned)(d * d);
}

// consumer of class c needs: (cls(h')==c) ? gop^2(h') : 0
__device__ __forceinline__ int scan_val(unsigned x, unsigned cbit15) {
    return ((x ^ cbit15) & 0x8000u) ? 0 : (int)(x & 0x7FFFu);
}

__global__ void __launch_bounds__(NTHR, 1) dice_kernel(
        const float* __restrict__ inp,
        const int*   __restrict__ tgt,
        float* __restrict__ out, int B) {
    const int b    = blockIdx.x / BLK_PER_B;
    const int wc0  = (blockIdx.x % BLK_PER_B) * COLS_PB;
    const int t    = threadIdx.x;          // 0..767
    const int lane = t & 31;
    const int warp = t >> 5;               // 0..23
    const int nblk = gridDim.x;

    const int h  = t >> 3;                 // 0..95 (this thread's row)
    const int wl = t & 7;                  // 0..7  (local column)
    const int wc = wc0 + wl;

    __shared__ unsigned       bitmap[HW / 32];     // 288 words: image as bits
    __shared__ unsigned short gcol[H * COLS_PB];   // gop^2 | (cls<<15)
    __shared__ float          wred[2][NTHR / 32];
    __shared__ int            cnt_s[NTHR / 32];
    __shared__ int            n1_s;

    // phase-B operand issued immediately (latency hidden under bitmap build)
    const float p = inp[b * HW + h * W + wc];

    // ---- build image bitmap: 3 int4 rounds + 8-lane shfl-OR packing -------
    const int4* tb4 = (const int4*)(tgt + b * HW);
    const int sub = 4 * (lane & 7);            // nibble position in word
    int cnt = 0;
#pragma unroll
    for (int i = 0; i < HW / (NTHR * 4); ++i) {        // 3 rounds
        const int4 v = tb4[i * NTHR + t];
        const unsigned nib = (unsigned)(v.x | (v.y << 1) | (v.z << 2) | (v.w << 3));
        cnt += __popc(nib);
        unsigned wrd = nib << sub;
        wrd |= __shfl_xor_sync(0xFFFFFFFFu, wrd, 1);
        wrd |= __shfl_xor_sync(0xFFFFFFFFu, wrd, 2);
        wrd |= __shfl_xor_sync(0xFFFFFFFFu, wrd, 4);
        if ((lane & 7) == 0) bitmap[i * (NTHR / 8) + (t >> 3)] = wrd;
    }
    cnt = __reduce_add_sync(0xFFFFFFFFu, cnt);
    if (lane == 0) cnt_s[warp] = cnt;
    __syncthreads();

    if (warp == 0) {                               // class-1 count (exact)
        int s = (lane < NTHR / 32) ? cnt_s[lane] : 0;
        s = __reduce_add_sync(0xFFFFFFFFu, s);
        if (lane == 0) n1_s = s;
    }

    // ---- row EDT: ONE opposite-class query per pixel (own-class dist = 0) -
    const unsigned long long lo =
        (unsigned long long)bitmap[h * 3] |
        ((unsigned long long)bitmap[h * 3 + 1] << 32);
    const unsigned long long hi = (unsigned long long)bitmap[h * 3 + 2];

    const int c = (wc < 64) ? (int)((lo >> wc) & 1ull)
                            : (int)((hi >> (wc - 64)) & 1ull);
    const int dq = nearest_bit_dist(c ? ~lo : lo,
                                    c ? ((~hi) & 0xFFFFFFFFull) : hi, wc);
    const unsigned e = pack_g(dq) | ((unsigned)c << 15);
    gcol[h * COLS_PB + wl] = (unsigned short)e;
    __syncthreads();

    const int n1 = n1_s;

    // ---- column scan: radii 1-2 unconditional, rare loop from r=3 ---------
    const unsigned cb = (unsigned)c << 15;
    const int bi = h * COLS_PB + wl;
    int best = (int)(e & 0x7FFFu);                       // r = 0 term
    const int vu1 = (h >= 1)     ? scan_val(gcol[bi - COLS_PB],     cb) : BIGV;
    const int vd1 = (h <= H - 2) ? scan_val(gcol[bi + COLS_PB],     cb) : BIGV;
    const int vu2 = (h >= 2)     ? scan_val(gcol[bi - 2 * COLS_PB], cb) : BIGV;
    const int vd2 = (h <= H - 3) ? scan_val(gcol[bi + 2 * COLS_PB], cb) : BIGV;
    best = min(best, min(1 + min(vu1, vd1), 4 + min(vu2, vd2)));
    for (int r = 3; r <= 95 && r * r < best; ++r) {
        const int rr = r * r;
        const int up = h - r, dn = h + r;
        if (up >= 0) best = min(best, rr + scan_val(gcol[up * COLS_PB + wl], cb));
        if (dn < H)  best = min(best, rr + scan_val(gcol[dn * COLS_PB + wl], cb));
    }

    // weight: 10*exp(-dmin/(2*5^2)); no opposite -> exp(-inf)=0; n1<=1 -> 1
    float wgt;
    if (n1 <= 1)           wgt = 1.0f;
    else if (best >= SENT) wgt = 0.0f;
    else                   wgt = 10.0f * __expf(-sqrtf((float)best) * 0.02f);

    const float tt = (float)c;
    float r1 = wgt * p * tt;
    float r2 = wgt * (p + tt);
#pragma unroll
    for (int off = 16; off; off >>= 1) {
        r1 += __shfl_down_sync(0xFFFFFFFFu, r1, off);
        r2 += __shfl_down_sync(0xFFFFFFFFu, r2, off);
    }
    if (lane == 0) { wred[0][warp] = r1; wred[1][warp] = r2; }
    __syncthreads();

    if (warp == 0) {
        float s1 = (lane < NTHR / 32) ? wred[0][lane] : 0.0f;
        float s2 = (lane < NTHR / 32) ? wred[1][lane] : 0.0f;
#pragma unroll
        for (int off = 16; off; off >>= 1) {
            s1 += __shfl_down_sync(0xFFFFFFFFu, s1, off);
            s2 += __shfl_down_sync(0xFFFFFFFFu, s2, off);
        }
        int last = 0;
        if (lane == 0) {
            // fire-and-forget accumulates (result unused -> RED); commutative
            // float adds, wobble ~1e-7 rel, far under the 1e-3 gate
            cuda::atomic_ref<float, cuda::thread_scope_device>
                a1(g_acc[b * 2 + 0]), a2(g_acc[b * 2 + 1]);
            a1.fetch_add(s1, cuda::memory_order_relaxed);
            a2.fetch_add(s2, cuda::memory_order_relaxed);
            // acq_rel: release orders this block's REDs; acquire on the
            // winning add makes all blocks' REDs visible. No L1-flush.
            cuda::atomic_ref<int, cuda::thread_scope_device> tk(g_ticket);
            last = (tk.fetch_add(1, cuda::memory_order_acq_rel) == nblk - 1);
        }
        last = __shfl_sync(0xFFFFFFFFu, last, 0);

        // ---- winner: one 16B readback, dice formula, cleanup --------------
        if (last && lane == 0) {
            float loss;
            if (B <= 2) {
                // single vector load; values stable (all REDs ordered before
                // the winning acquire), no stale L1 copy possible (this block
                // never loaded these lines; L1 is flushed per launch).
                const float4 acc = *reinterpret_cast<const float4*>(g_acc);
                loss = 1.0f - (2.0f * acc.x + 1.0f) / (acc.y + 1.0f);
                if (B == 2)
                    loss += 1.0f - (2.0f * acc.z + 1.0f) / (acc.w + 1.0f);
                *reinterpret_cast<float4*>(g_acc) =
                    make_float4(0.0f, 0.0f, 0.0f, 0.0f);    // next replay
            } else {
                loss = 0.0f;
                for (int bb = 0; bb < B; ++bb) {
                    const float n = g_acc[bb * 2 + 0];
                    const float d = g_acc[bb * 2 + 1];
                    loss += 1.0f - (2.0f * n + 1.0f) / (d + 1.0f);
                    g_acc[bb * 2 + 0] = 0.0f;
                    g_acc[bb * 2 + 1] = 0.0f;
                }
            }
            out[0] = loss;
            g_ticket = 0;                                  // replay-safe reset
        }
    }
}

extern "C" void kernel_launch(void* const* d_in, const int* in_sizes, int n_in,
                              void* d_out, int out_size) {
    const float* inp = (const float*)d_in[0];   // inputs  [B,1,96,96] float32
    const int*   tgt = (const int*)  d_in[1];   // targets [B,1,96,96] int32
    const int B = in_sizes[1] / HW;

    dice_kernel<<<B * BLK_PER_B, NTHR>>>(inp, tgt, (float*)d_out, B);
}